// round 5
// baseline (speedup 1.0000x reference)
#include <cuda_runtime.h>
#include <cstdint>

#define S_LEN 128
#define B_SZ  32
#define H_DIM 1024
#define V_SZ  32000
#define SB    4096      // S*B
#define BH    32768     // B*H

typedef unsigned long long u64;

// ---- packed f32x2 (Blackwell FFMA2 path, PTX-only) ----
__device__ __forceinline__ void ffma2(u64 &c, u64 a, u64 b){
  asm("fma.rn.f32x2 %0, %1, %2, %0;" : "+l"(c) : "l"(a), "l"(b));
}
__device__ __forceinline__ u64 addf2(u64 a, u64 b){
  u64 r; asm("add.rn.f32x2 %0, %1, %2;" : "=l"(r) : "l"(a), "l"(b)); return r;
}
__device__ __forceinline__ u64 pack2(float lo, float hi){
  u64 r; asm("mov.b64 %0, {%1, %2};" : "=l"(r) : "f"(lo), "f"(hi)); return r;
}
__device__ __forceinline__ float2 unpack2(u64 v){
  float lo, hi; asm("mov.b64 {%0, %1}, %2;" : "=f"(lo), "=f"(hi) : "l"(v));
  return make_float2(lo, hi);
}

// ---- device-global scratch (no allocation allowed) ----
__device__ float g_X  [SB*H_DIM];
__device__ float g_xi [SB*H_DIM];
__device__ float g_xf [SB*H_DIM];
__device__ float g_l1 [SB*H_DIM];
__device__ float g_l2 [SB*H_DIM];
__device__ float g_lat0[BH];
__device__ float g_lat1[BH];

// ============================================================
// Embedding gather: X[s*B+b, :] = emb[word[s,b], :]
// ============================================================
__global__ void gather_kernel(const int* __restrict__ word,
                              const float* __restrict__ emb,
                              float* __restrict__ X) {
  int i = blockIdx.x * blockDim.x + threadIdx.x;   // float4 index
  int row = i >> 8;                                // 256 float4 per row (E=1024)
  int col = i & 255;
  int w = word[row];
  reinterpret_cast<float4*>(X)[i] =
      reinterpret_cast<const float4*>(emb + (size_t)w * H_DIM)[col];
}

// ============================================================
// GEMM (NT): C[M,N] = A[M,K] * Bw[N,K]^T + bias[N]
// 128x128 tile, BK=16, 256 threads, 8x8 micro via FFMA2.
// M,N multiples of 128; K multiple of 16.
// ============================================================
__global__ __launch_bounds__(256)
void gemm_nt_bias(const float* __restrict__ A, const float* __restrict__ Bw,
                  const float* __restrict__ bias, float* __restrict__ C,
                  int N, int K) {
  __shared__ __align__(16) float As[16][132];   // row stride 528B = 33*16 (aligned)
  __shared__ __align__(16) float Bs[16][132];
  const int tid = threadIdx.x;
  const int bn = blockIdx.x * 128, bm = blockIdx.y * 128;
  const int tx = tid & 15, ty = tid >> 4;
  u64 acc[8][4] = {};

  for (int kk = 0; kk < K; kk += 16) {
    #pragma unroll
    for (int l = 0; l < 2; l++) {
      int slot = tid + l*256;                 // 0..511
      int m = slot >> 2, kq = (slot & 3) * 4;
      float4 va = *reinterpret_cast<const float4*>(A + (size_t)(bm+m)*K + kk + kq);
      As[kq+0][m]=va.x; As[kq+1][m]=va.y; As[kq+2][m]=va.z; As[kq+3][m]=va.w;
      float4 vb = *reinterpret_cast<const float4*>(Bw + (size_t)(bn+m)*K + kk + kq);
      Bs[kq+0][m]=vb.x; Bs[kq+1][m]=vb.y; Bs[kq+2][m]=vb.z; Bs[kq+3][m]=vb.w;
    }
    __syncthreads();
    #pragma unroll
    for (int k = 0; k < 16; k++) {
      float4 a0 = *reinterpret_cast<const float4*>(&As[k][ty*4]);
      float4 a1 = *reinterpret_cast<const float4*>(&As[k][64 + ty*4]);
      ulonglong2 b0 = *reinterpret_cast<const ulonglong2*>(&Bs[k][tx*4]);
      ulonglong2 b1 = *reinterpret_cast<const ulonglong2*>(&Bs[k][64 + tx*4]);
      u64 bv[4] = {b0.x, b0.y, b1.x, b1.y};
      float am[8] = {a0.x,a0.y,a0.z,a0.w, a1.x,a1.y,a1.z,a1.w};
      #pragma unroll
      for (int i = 0; i < 8; i++) {
        u64 ad = pack2(am[i], am[i]);
        #pragma unroll
        for (int j = 0; j < 4; j++) ffma2(acc[i][j], ad, bv[j]);
      }
    }
    __syncthreads();
  }

  #pragma unroll
  for (int i = 0; i < 8; i++) {
    int m = bm + ((i < 4) ? (ty*4 + i) : (64 + ty*4 + i - 4));
    float* cp = C + (size_t)m * N + bn;
    #pragma unroll
    for (int j = 0; j < 4; j++) {
      int n0 = ((j & 2) ? 64 : 0) + tx*4 + ((j & 1) ? 2 : 0);
      float2 v = unpack2(acc[i][j]);
      v.x += bias[bn + n0];
      v.y += bias[bn + n0 + 1];
      *reinterpret_cast<float2*>(cp + n0) = v;
    }
  }
}

// ============================================================
// One RAN recurrence step (both gates + update fused).
// Block owns 8 g columns (16 gc = g x {i,f}); 128 blocks, 256 threads.
// Warp-split-K with FFMA2 over b-pairs; shfl + smem reduction; epilogue
// applies sigmoid gates and additive update, writes latB/seq (+last-step outs).
// ============================================================
__global__ __launch_bounds__(256)
void ran_step(const float* __restrict__ latA, float* __restrict__ latB,
              const float* __restrict__ Wi, const float* __restrict__ Wf,
              const float* __restrict__ xi, const float* __restrict__ xf,
              const float* __restrict__ x, float* __restrict__ seq_out,
              float* __restrict__ ig_out, float* __restrict__ fg_out,
              float* __restrict__ lat_out)
{
  __shared__ __align__(16) float smem[16*132 + 128*36];   // 6720 floats
  float* Ws = smem;                                        // [16][132]
  float (*latT)[36] = (float(*)[36])(smem + 16*132);       // [128][36]
  float (*part)[36] = (float(*)[36])smem;                  // overlay [128][36]

  const int tid = threadIdx.x, lane = tid & 31, warp = tid >> 5;
  const int gblk = blockIdx.x * 8;
  const int gc = lane & 15;                        // 2*g_local + gate
  const int slice = (warp << 1) | (lane >> 4);     // 0..15 K-slices
  u64 acc[16] = {};                                // 32 b accumulators (f32x2)

  for (int c = 0; c < 8; c++) {                    // K chunks of 128
    // cooperative W tile load (coalesced): 16 rows x 128
    #pragma unroll
    for (int l = 0; l < 2; l++) {
      int idx = tid + l*256;                       // float4 slots
      int row = idx >> 5, c4 = (idx & 31) * 4;
      const float* wr = ((row & 1) ? Wf : Wi) + (size_t)(gblk + (row >> 1)) * H_DIM;
      *reinterpret_cast<float4*>(&Ws[row*132 + c4]) =
          *reinterpret_cast<const float4*>(wr + c*128 + c4);
    }
    // latent chunk transposed: latT[k][b]
    {
      int b = lane, k0 = warp * 16;
      #pragma unroll
      for (int q = 0; q < 4; q++) {
        float4 v = *reinterpret_cast<const float4*>(
            latA + (size_t)b*H_DIM + c*128 + k0 + q*4);
        latT[k0+q*4+0][b]=v.x; latT[k0+q*4+1][b]=v.y;
        latT[k0+q*4+2][b]=v.z; latT[k0+q*4+3][b]=v.w;
      }
    }
    __syncthreads();
    #pragma unroll
    for (int j = 0; j < 8; j++) {
      int k = slice*8 + j;
      float w = Ws[gc*132 + k];
      u64 wp = pack2(w, w);
      #pragma unroll
      for (int m = 0; m < 8; m++) {                // broadcast LDS.128 of b-pairs
        ulonglong2 lp = *reinterpret_cast<const ulonglong2*>(&latT[k][m*4]);
        ffma2(acc[2*m],   wp, lp.x);
        ffma2(acc[2*m+1], wp, lp.y);
      }
    }
    __syncthreads();
  }

  // combine lanes l and l^16 (same gc, adjacent slices)
  #pragma unroll
  for (int i = 0; i < 16; i++)
    acc[i] = addf2(acc[i], __shfl_xor_sync(0xffffffffu, acc[i], 16));
  if (lane < 16) {
    #pragma unroll
    for (int m = 0; m < 8; m++) {
      ulonglong2 v; v.x = acc[2*m]; v.y = acc[2*m+1];
      *reinterpret_cast<ulonglong2*>(&part[warp*16 + gc][m*4]) = v;
    }
  }
  __syncthreads();

  // reduce 8 warp-partials + gates + update: thread -> (b, g_local)
  {
    int b = tid & 31, gl = tid >> 5;
    float si = 0.f, sf = 0.f;
    #pragma unroll
    for (int w8 = 0; w8 < 8; w8++) {
      si += part[w8*16 + 2*gl    ][b];
      sf += part[w8*16 + 2*gl + 1][b];
    }
    int idx = b * H_DIM + gblk + gl;
    si += xi[idx]; sf += xf[idx];
    float ig = 1.f / (1.f + expf(-si));
    float fg = 1.f / (1.f + expf(-sf));
    float nl = ig * x[idx] + fg * latA[idx];
    latB[idx] = nl;
    seq_out[idx] = nl;
    if (ig_out) { ig_out[idx] = ig; fg_out[idx] = fg; lat_out[idx] = nl; }
  }
}

// ============================================================
extern "C" void kernel_launch(void* const* d_in, const int* in_sizes, int n_in,
                              void* d_out, int out_size) {
  const int*   word   = (const int*)  d_in[0];
  const float* lat_in = (const float*)d_in[1];
  const float* emb    = (const float*)d_in[2];
  const float* h2o_w  = (const float*)d_in[3];
  const float* h2o_b  = (const float*)d_in[4];
  const float* Whi    = (const float*)d_in[5];
  const float* Wxi_w  = (const float*)d_in[6];
  const float* Wxi_b  = (const float*)d_in[7];
  const float* Whf    = (const float*)d_in[8];
  const float* Wxf_w  = (const float*)d_in[9];
  const float* Wxf_b  = (const float*)d_in[10];
  const float* Whi2   = (const float*)d_in[11];
  const float* Wxi2_w = (const float*)d_in[12];
  const float* Wxi2_b = (const float*)d_in[13];
  const float* Whf2   = (const float*)d_in[14];
  const float* Wxf2_w = (const float*)d_in[15];
  const float* Wxf2_b = (const float*)d_in[16];

  float* out        = (float*)d_out;
  float* out_lat    = out;                            // [1,B,H]
  float* out_logits = out + BH;                       // [S,B,V]
  float* out_ig     = out + BH + (size_t)SB * V_SZ;   // [1,B,H]
  float* out_fg     = out_ig + BH;                    // [1,B,H]

  float *X, *XI, *XF, *L1, *L2, *LAT0, *LAT1;
  cudaGetSymbolAddress((void**)&X,    g_X);
  cudaGetSymbolAddress((void**)&XI,   g_xi);
  cudaGetSymbolAddress((void**)&XF,   g_xf);
  cudaGetSymbolAddress((void**)&L1,   g_l1);
  cudaGetSymbolAddress((void**)&L2,   g_l2);
  cudaGetSymbolAddress((void**)&LAT0, g_lat0);
  cudaGetSymbolAddress((void**)&LAT1, g_lat1);

  // 1) embed
  gather_kernel<<<4096, 256>>>(word, emb, X);

  dim3 gg(H_DIM/128, SB/128);   // (8, 32)

  // 2) layer-1 gate pre-activations
  gemm_nt_bias<<<gg, 256>>>(X, Wxi_w, Wxi_b, XI, H_DIM, H_DIM);
  gemm_nt_bias<<<gg, 256>>>(X, Wxf_w, Wxf_b, XF, H_DIM, H_DIM);

  // 3) layer-1 recurrence
  const float* cur = lat_in;
  for (int t = 0; t < S_LEN; t++) {
    float* nxt = (t & 1) ? LAT0 : LAT1;
    ran_step<<<128, 256>>>(cur, nxt, Whi, Whf,
                           XI + (size_t)t*BH, XF + (size_t)t*BH,
                           X  + (size_t)t*BH, L1 + (size_t)t*BH,
                           nullptr, nullptr, nullptr);
    cur = nxt;
  }

  // 4) layer-2 gate pre-activations (reuse XI/XF)
  gemm_nt_bias<<<gg, 256>>>(L1, Wxi2_w, Wxi2_b, XI, H_DIM, H_DIM);
  gemm_nt_bias<<<gg, 256>>>(L1, Wxf2_w, Wxf2_b, XF, H_DIM, H_DIM);

  // 5) layer-2 recurrence (latent carries over from layer 1)
  for (int t = 0; t < S_LEN; t++) {
    float* nxt = (t & 1) ? LAT0 : LAT1;
    bool last = (t == S_LEN - 1);
    ran_step<<<128, 256>>>(cur, nxt, Whi2, Whf2,
                           XI + (size_t)t*BH, XF + (size_t)t*BH,
                           L1 + (size_t)t*BH, L2 + (size_t)t*BH,
                           last ? out_ig : nullptr,
                           last ? out_fg : nullptr,
                           last ? out_lat : nullptr);
    cur = nxt;
  }

  // 6) logits GEMM: [4096,1024] x [32000,1024]^T + bias
  dim3 gl(V_SZ/128, SB/128);    // (250, 32)
  gemm_nt_bias<<<gl, 256>>>(L2, h2o_w, h2o_b, out_logits, V_SZ, H_DIM);
}

// round 8
// speedup vs baseline: 1.0132x; 1.0132x over previous
#include <cuda_runtime.h>
#include <cstdint>

#define S_LEN 128
#define B_SZ  32
#define H_DIM 1024
#define V_SZ  32000
#define SB    4096      // S*B
#define BH    32768     // B*H

typedef unsigned long long u64;

// ---- packed f32x2 (Blackwell FFMA2 path, PTX-only) ----
__device__ __forceinline__ void ffma2(u64 &c, u64 a, u64 b){
  asm("fma.rn.f32x2 %0, %1, %2, %0;" : "+l"(c) : "l"(a), "l"(b));
}
__device__ __forceinline__ u64 addf2(u64 a, u64 b){
  u64 r; asm("add.rn.f32x2 %0, %1, %2;" : "=l"(r) : "l"(a), "l"(b)); return r;
}
__device__ __forceinline__ u64 pack2(float lo, float hi){
  u64 r; asm("mov.b64 %0, {%1, %2};" : "=l"(r) : "f"(lo), "f"(hi)); return r;
}
__device__ __forceinline__ float2 unpack2(u64 v){
  float lo, hi; asm("mov.b64 {%0, %1}, %2;" : "=f"(lo), "=f"(hi) : "l"(v));
  return make_float2(lo, hi);
}
__device__ __forceinline__ unsigned ld_acq(const unsigned* p){
  unsigned v;
  asm volatile("ld.acquire.gpu.u32 %0, [%1];" : "=r"(v) : "l"(p) : "memory");
  return v;
}

// ---- device-global scratch (no allocation allowed) ----
__device__ float g_X  [SB*H_DIM];
__device__ float g_xi [SB*H_DIM];
__device__ float g_xf [SB*H_DIM];
__device__ float g_l1 [SB*H_DIM];
__device__ float g_l2 [SB*H_DIM];
__device__ float g_lat0[BH];
__device__ float g_lat1[BH];
__device__ unsigned g_bar;      // zero-initialized; self-resetting
__device__ unsigned g_depart;

// ============================================================
// Embedding gather: X[s*B+b, :] = emb[word[s,b], :]
// ============================================================
__global__ void gather_kernel(const int* __restrict__ word,
                              const float* __restrict__ emb,
                              float* __restrict__ X) {
  int i = blockIdx.x * blockDim.x + threadIdx.x;   // float4 index
  int row = i >> 8;                                // 256 float4 per row (E=1024)
  int col = i & 255;
  int w = word[row];
  reinterpret_cast<float4*>(X)[i] =
      reinterpret_cast<const float4*>(emb + (size_t)w * H_DIM)[col];
}

// ============================================================
// GEMM (NT): C[M,N] = A[M,K] * Bw[N,K]^T + bias[N]
// 128x128 tile, BK=16, 256 threads, 8x8 micro via FFMA2.
// ============================================================
__global__ __launch_bounds__(256)
void gemm_nt_bias(const float* __restrict__ A, const float* __restrict__ Bw,
                  const float* __restrict__ bias, float* __restrict__ C,
                  int N, int K) {
  __shared__ __align__(16) float As[16][132];
  __shared__ __align__(16) float Bs[16][132];
  const int tid = threadIdx.x;
  const int bn = blockIdx.x * 128, bm = blockIdx.y * 128;
  const int tx = tid & 15, ty = tid >> 4;
  u64 acc[8][4] = {};

  for (int kk = 0; kk < K; kk += 16) {
    #pragma unroll
    for (int l = 0; l < 2; l++) {
      int slot = tid + l*256;
      int m = slot >> 2, kq = (slot & 3) * 4;
      float4 va = *reinterpret_cast<const float4*>(A + (size_t)(bm+m)*K + kk + kq);
      As[kq+0][m]=va.x; As[kq+1][m]=va.y; As[kq+2][m]=va.z; As[kq+3][m]=va.w;
      float4 vb = *reinterpret_cast<const float4*>(Bw + (size_t)(bn+m)*K + kk + kq);
      Bs[kq+0][m]=vb.x; Bs[kq+1][m]=vb.y; Bs[kq+2][m]=vb.z; Bs[kq+3][m]=vb.w;
    }
    __syncthreads();
    #pragma unroll
    for (int k = 0; k < 16; k++) {
      float4 a0 = *reinterpret_cast<const float4*>(&As[k][ty*4]);
      float4 a1 = *reinterpret_cast<const float4*>(&As[k][64 + ty*4]);
      ulonglong2 b0 = *reinterpret_cast<const ulonglong2*>(&Bs[k][tx*4]);
      ulonglong2 b1 = *reinterpret_cast<const ulonglong2*>(&Bs[k][64 + tx*4]);
      u64 bv[4] = {b0.x, b0.y, b1.x, b1.y};
      float am[8] = {a0.x,a0.y,a0.z,a0.w, a1.x,a1.y,a1.z,a1.w};
      #pragma unroll
      for (int i = 0; i < 8; i++) {
        u64 ad = pack2(am[i], am[i]);
        #pragma unroll
        for (int j = 0; j < 4; j++) ffma2(acc[i][j], ad, bv[j]);
      }
    }
    __syncthreads();
  }

  #pragma unroll
  for (int i = 0; i < 8; i++) {
    int m = bm + ((i < 4) ? (ty*4 + i) : (64 + ty*4 + i - 4));
    float* cp = C + (size_t)m * N + bn;
    #pragma unroll
    for (int j = 0; j < 4; j++) {
      int n0 = ((j & 2) ? 64 : 0) + tx*4 + ((j & 1) ? 2 : 0);
      float2 v = unpack2(acc[i][j]);
      v.x += bias[bn + n0];
      v.y += bias[bn + n0 + 1];
      *reinterpret_cast<float2*>(cp + n0) = v;
    }
  }
}

// ============================================================
// Persistent RAN layer: all 128 steps in one kernel.
// Grid = 128 blocks (all co-resident), software grid barrier per step.
// W tile (16 rows x 1024 = 64KB) resident in smem for the whole layer.
// Dynamic smem: Ws[16][1028] + latT[128][36] = 84224 bytes.
// ============================================================
#define WS_STRIDE 1028
#define RAN_SMEM ((16*WS_STRIDE + 128*36) * 4)

__global__ __launch_bounds__(256)
void ran_layer(const float* __restrict__ init,
               float* __restrict__ lat0, float* __restrict__ lat1,
               const float* __restrict__ Wi, const float* __restrict__ Wf,
               const float* __restrict__ xi_all, const float* __restrict__ xf_all,
               const float* __restrict__ x_all, float* __restrict__ seq_all,
               float* __restrict__ ig_out, float* __restrict__ fg_out,
               float* __restrict__ lat_out)
{
  extern __shared__ __align__(16) float smem[];
  float* Ws = smem;                                        // [16][1028]
  float (*latT)[36] = (float(*)[36])(smem + 16*WS_STRIDE); // [128][36]
  float (*part)[36] = latT;                                // overlay after sync

  const int tid  = threadIdx.x, lane = tid & 31, warp = tid >> 5;
  const int gblk = blockIdx.x * 8;
  const int gc    = lane & 15;                    // 2*g_local + gate
  const int slice = (warp << 1) | (lane >> 4);    // 0..15 K-slices

  // ---- load W tile once (16 rows x 1024) ----
  for (int i = tid; i < 16*256; i += 256) {       // float4 slots
    int row = i >> 8, c4 = (i & 255) * 4;
    const float* wr = ((row & 1) ? Wf : Wi) + (size_t)(gblk + (row >> 1)) * H_DIM;
    *reinterpret_cast<float4*>(&Ws[row*WS_STRIDE + c4]) =
        *reinterpret_cast<const float4*>(wr + c4);
  }
  __syncthreads();

  for (int t = 0; t < S_LEN; t++) {
    const float* latA = (t == 0) ? init : ((t & 1) ? lat1 : lat0);
    float*       latB = (t & 1) ? lat0 : lat1;
    const float* xi = xi_all + (size_t)t * BH;
    const float* xf = xf_all + (size_t)t * BH;
    const float* x  = x_all  + (size_t)t * BH;
    float*      seq = seq_all + (size_t)t * BH;

    u64 acc[16] = {};
    for (int c = 0; c < 8; c++) {                 // K chunks of 128
      {                                           // stage latT[k][b]
        int b = lane, k0 = warp * 16;
        #pragma unroll
        for (int q = 0; q < 4; q++) {
          float4 v = *reinterpret_cast<const float4*>(
              latA + (size_t)b*H_DIM + c*128 + k0 + q*4);
          latT[k0+q*4+0][b]=v.x; latT[k0+q*4+1][b]=v.y;
          latT[k0+q*4+2][b]=v.z; latT[k0+q*4+3][b]=v.w;
        }
      }
      __syncthreads();
      #pragma unroll
      for (int j = 0; j < 8; j++) {
        int k = slice*8 + j;
        float w = Ws[gc*WS_STRIDE + c*128 + k];
        u64 wp = pack2(w, w);
        #pragma unroll
        for (int m = 0; m < 8; m++) {             // broadcast LDS.128 b-pairs
          ulonglong2 lp = *reinterpret_cast<const ulonglong2*>(&latT[k][m*4]);
          ffma2(acc[2*m],   wp, lp.x);
          ffma2(acc[2*m+1], wp, lp.y);
        }
      }
      __syncthreads();
    }

    // combine lanes l and l^16 (same gc, adjacent slices)
    #pragma unroll
    for (int i = 0; i < 16; i++)
      acc[i] = addf2(acc[i], __shfl_xor_sync(0xffffffffu, acc[i], 16));
    if (lane < 16) {
      #pragma unroll
      for (int m = 0; m < 8; m++) {
        ulonglong2 v; v.x = acc[2*m]; v.y = acc[2*m+1];
        *reinterpret_cast<ulonglong2*>(&part[warp*16 + gc][m*4]) = v;
      }
    }
    __syncthreads();

    // reduce 8 warp-partials + gates + update: thread -> (b, g_local)
    {
      int b = tid & 31, gl = tid >> 5;
      float si = 0.f, sf = 0.f;
      #pragma unroll
      for (int w8 = 0; w8 < 8; w8++) {
        si += part[w8*16 + 2*gl    ][b];
        sf += part[w8*16 + 2*gl + 1][b];
      }
      int idx = b * H_DIM + gblk + gl;
      si += xi[idx]; sf += xf[idx];
      float ig = 1.f / (1.f + __expf(-si));
      float fg = 1.f / (1.f + __expf(-sf));
      float nl = ig * x[idx] + fg * latA[idx];
      latB[idx] = nl;
      seq[idx]  = nl;
      if (t == S_LEN-1 && ig_out) {
        ig_out[idx] = ig; fg_out[idx] = fg; lat_out[idx] = nl;
      }
    }

    // ---- software grid barrier (release -> arrive -> acquire spin) ----
    __threadfence();
    __syncthreads();
    if (tid == 0) {
      atomicAdd(&g_bar, 1u);
      unsigned target = (unsigned)(t + 1) * 128u;
      while (ld_acq(&g_bar) < target) { }
    }
    __syncthreads();
  }

  // self-reset so next launch / graph replay starts from zero
  if (tid == 0) {
    unsigned old = atomicAdd(&g_depart, 1u);
    if (old == 127u) {
      atomicExch(&g_bar, 0u);
      atomicExch(&g_depart, 0u);
    }
  }
}

// ============================================================
extern "C" void kernel_launch(void* const* d_in, const int* in_sizes, int n_in,
                              void* d_out, int out_size) {
  const int*   word   = (const int*)  d_in[0];
  const float* lat_in = (const float*)d_in[1];
  const float* emb    = (const float*)d_in[2];
  const float* h2o_w  = (const float*)d_in[3];
  const float* h2o_b  = (const float*)d_in[4];
  const float* Whi    = (const float*)d_in[5];
  const float* Wxi_w  = (const float*)d_in[6];
  const float* Wxi_b  = (const float*)d_in[7];
  const float* Whf    = (const float*)d_in[8];
  const float* Wxf_w  = (const float*)d_in[9];
  const float* Wxf_b  = (const float*)d_in[10];
  const float* Whi2   = (const float*)d_in[11];
  const float* Wxi2_w = (const float*)d_in[12];
  const float* Wxi2_b = (const float*)d_in[13];
  const float* Whf2   = (const float*)d_in[14];
  const float* Wxf2_w = (const float*)d_in[15];
  const float* Wxf2_b = (const float*)d_in[16];

  float* out        = (float*)d_out;
  float* out_lat    = out;                            // [1,B,H]
  float* out_logits = out + BH;                       // [S,B,V]
  float* out_ig     = out + BH + (size_t)SB * V_SZ;   // [1,B,H]
  float* out_fg     = out_ig + BH;                    // [1,B,H]

  float *X, *XI, *XF, *L1, *L2, *LAT0, *LAT1;
  cudaGetSymbolAddress((void**)&X,    g_X);
  cudaGetSymbolAddress((void**)&XI,   g_xi);
  cudaGetSymbolAddress((void**)&XF,   g_xf);
  cudaGetSymbolAddress((void**)&L1,   g_l1);
  cudaGetSymbolAddress((void**)&L2,   g_l2);
  cudaGetSymbolAddress((void**)&LAT0, g_lat0);
  cudaGetSymbolAddress((void**)&LAT1, g_lat1);

  cudaFuncSetAttribute(ran_layer, cudaFuncAttributeMaxDynamicSharedMemorySize,
                       RAN_SMEM);

  // 1) embed
  gather_kernel<<<4096, 256>>>(word, emb, X);

  dim3 gg(H_DIM/128, SB/128);   // (8, 32)

  // 2) layer-1 gate pre-activations
  gemm_nt_bias<<<gg, 256>>>(X, Wxi_w, Wxi_b, XI, H_DIM, H_DIM);
  gemm_nt_bias<<<gg, 256>>>(X, Wxf_w, Wxf_b, XF, H_DIM, H_DIM);

  // 3) layer-1 recurrence (persistent, 128 steps); final latent -> LAT0
  ran_layer<<<128, 256, RAN_SMEM>>>(lat_in, LAT0, LAT1, Whi, Whf,
                                    XI, XF, X, L1,
                                    nullptr, nullptr, nullptr);

  // 4) layer-2 gate pre-activations (reuse XI/XF)
  gemm_nt_bias<<<gg, 256>>>(L1, Wxi2_w, Wxi2_b, XI, H_DIM, H_DIM);
  gemm_nt_bias<<<gg, 256>>>(L1, Wxf2_w, Wxf2_b, XF, H_DIM, H_DIM);

  // 5) layer-2 recurrence (latent carried from layer 1 = LAT0)
  ran_layer<<<128, 256, RAN_SMEM>>>(LAT0, LAT0, LAT1, Whi2, Whf2,
                                    XI, XF, L1, L2,
                                    out_ig, out_fg, out_lat);

  // 6) logits GEMM: [4096,1024] x [32000,1024]^T + bias
  dim3 gl(V_SZ/128, SB/128);    // (250, 32)
  gemm_nt_bias<<<gl, 256>>>(L2, h2o_w, h2o_b, out_logits, V_SZ, H_DIM);
}